// round 10
// baseline (speedup 1.0000x reference)
#include <cuda_runtime.h>
#include <cstdint>
#include <cstddef>

#define T_STEPS 32768
#define CD 512
#define ID 1024
#define NG 2048
#define NB   64
#define TPB  256
#define JPB  8            // h indices per CTA
#define NROWS 32          // 4 gates * JPB rows per CTA
#define KW   16           // ulonglong2 (4 floats) chunks per lane
#define NCTR 8            // arrival counters (8 CTAs each)
#define CSTRIDE 32        // counter stride in uints (=128B line)

// ---------------- device-global scratch ------------------------------------
__device__ float g_gx[(size_t)T_STEPS * NG];   // precomputed Wx@x + b, [T][2048]
__device__ float g_hbuf[2][CD];                // double-buffered h (plain data)
__device__ unsigned int g_counters[NCTR * CSTRIDE];  // split arrival counters, 128B apart

// ---------------- morally-strong accessors ----------------------------------
__device__ __forceinline__ unsigned int ld_acq32(const unsigned int* p) {
    unsigned int v;
    asm volatile("ld.acquire.gpu.global.u32 %0, [%1];" : "=r"(v) : "l"(p) : "memory");
    return v;
}
__device__ __forceinline__ void red_rel_add(unsigned int* p, unsigned int v) {
    asm volatile("red.release.gpu.global.add.u32 [%0], %1;" :: "l"(p), "r"(v) : "memory");
}

// ---------------- GEMM (+ inlined state reset in block (0,0)) ---------------
#define GBM 128
#define GBN 128
#define GBK 8

__global__ __launch_bounds__(256) void gemm_gx_kernel(
    const float* __restrict__ x,
    const float* __restrict__ wf_w, const float* __restrict__ wf_b,
    const float* __restrict__ wi_w, const float* __restrict__ wi_b,
    const float* __restrict__ wc_w, const float* __restrict__ wc_b,
    const float* __restrict__ wo_w, const float* __restrict__ wo_b)
{
    // ---- state reset (replaces init_kernel; rec runs only after this grid)
    if (blockIdx.x == 0 && blockIdx.y == 0) {
        int i = threadIdx.x;
        if (i < 2 * CD) (&g_hbuf[0][0])[i] = 0.0f;       // h(0) = 0, both buffers
        if (i < NCTR * CSTRIDE) g_counters[i] = 0u;      // counters = 0
    }

    __shared__ float As[GBK][GBM];
    __shared__ float Bs[GBK][GBN];

    const int tid = threadIdx.x;
    const int tx = tid & 15;
    const int ty = tid >> 4;
    const int r0 = blockIdx.x * GBN;
    const int t0 = blockIdx.y * GBM;
    const int gate = r0 >> 9;
    const int rbase = r0 & 511;

    const float* wsrc = (gate == 0) ? wf_w : (gate == 1) ? wi_w : (gate == 2) ? wc_w : wo_w;
    const float* bsrc = (gate == 0) ? wf_b : (gate == 1) ? wi_b : (gate == 2) ? wc_b : wo_b;

    const int lrow = tid >> 1;
    const int lk4  = (tid & 1) * 4;

    float acc[8][8];
    #pragma unroll
    for (int i = 0; i < 8; i++)
        #pragma unroll
        for (int j = 0; j < 8; j++) acc[i][j] = 0.0f;

    for (int k0 = 0; k0 < CD; k0 += GBK) {
        float4 av = *(const float4*)(x    + (size_t)(t0 + lrow) * CD + k0 + lk4);
        float4 bv = *(const float4*)(wsrc + (size_t)(rbase + lrow) * ID + k0 + lk4);
        __syncthreads();
        As[lk4 + 0][lrow] = av.x; As[lk4 + 1][lrow] = av.y;
        As[lk4 + 2][lrow] = av.z; As[lk4 + 3][lrow] = av.w;
        Bs[lk4 + 0][lrow] = bv.x; Bs[lk4 + 1][lrow] = bv.y;
        Bs[lk4 + 2][lrow] = bv.z; Bs[lk4 + 3][lrow] = bv.w;
        __syncthreads();
        #pragma unroll
        for (int k = 0; k < GBK; k++) {
            const float4* As4 = (const float4*)As[k];
            const float4* Bs4 = (const float4*)Bs[k];
            float4 a0 = As4[ty], a1 = As4[16 + ty];
            float4 b0 = Bs4[tx], b1 = Bs4[16 + tx];
            float ar[8] = {a0.x, a0.y, a0.z, a0.w, a1.x, a1.y, a1.z, a1.w};
            float br[8] = {b0.x, b0.y, b0.z, b0.w, b1.x, b1.y, b1.z, b1.w};
            #pragma unroll
            for (int i = 0; i < 8; i++)
                #pragma unroll
                for (int j = 0; j < 8; j++) acc[i][j] += ar[i] * br[j];
        }
    }

    float4 bias0 = *(const float4*)(bsrc + rbase + tx * 4);
    float4 bias1 = *(const float4*)(bsrc + rbase + 64 + tx * 4);
    float bb[8] = {bias0.x, bias0.y, bias0.z, bias0.w, bias1.x, bias1.y, bias1.z, bias1.w};

    #pragma unroll
    for (int i = 0; i < 8; i++) {
        int trow = t0 + ((i < 4) ? (ty * 4 + i) : (64 + ty * 4 + i - 4));
        float4 o0, o1;
        o0.x = acc[i][0] + bb[0]; o0.y = acc[i][1] + bb[1];
        o0.z = acc[i][2] + bb[2]; o0.w = acc[i][3] + bb[3];
        o1.x = acc[i][4] + bb[4]; o1.y = acc[i][5] + bb[5];
        o1.z = acc[i][6] + bb[6]; o1.w = acc[i][7] + bb[7];
        *(float4*)(g_gx + (size_t)trow * NG + r0 + tx * 4)      = o0;
        *(float4*)(g_gx + (size_t)trow * NG + r0 + 64 + tx * 4) = o1;
    }
}

// ---------------- persistent recurrent kernel --------------------------------
__device__ __forceinline__ unsigned long long ffma2(
    unsigned long long a, unsigned long long b, unsigned long long c) {
    unsigned long long d;
    asm ("fma.rn.f32x2 %0, %1, %2, %3;" : "=l"(d) : "l"(a), "l"(b), "l"(c));
    return d;
}
__device__ __forceinline__ float2 unpack2(unsigned long long a) {
    float2 r;
    asm ("mov.b64 {%0, %1}, %2;" : "=f"(r.x), "=f"(r.y) : "l"(a));
    return r;
}
__device__ __forceinline__ float sigmoid_f(float x) {
    return __fdividef(1.0f, 1.0f + __expf(-x));
}
__device__ __forceinline__ float tanh_f(float x) {
    float ax = fabsf(x);
    float e  = __expf(-2.0f * ax);
    float t  = __fdividef(1.0f - e, 1.0f + e);
    return copysignf(t, x);
}

__global__ __launch_bounds__(TPB, 1) void lstm_rec_kernel(
    const float* __restrict__ wf_w, const float* __restrict__ wi_w,
    const float* __restrict__ wc_w, const float* __restrict__ wo_w,
    float* __restrict__ d_out)
{
    __shared__ __align__(16) float hsf[CD];   // h(t) broadcast
    __shared__ float gsm[NROWS];              // per-row recurrent dots

    const ulonglong2* hs = (const ulonglong2*)hsf;
    float4* hs4 = (float4*)hsf;

    const int tid  = threadIdx.x;
    const int r    = tid >> 3;          // local row 0..31
    const int c    = tid & 7;           // lane within row
    const int gate = r >> 3;
    const int jj   = r & 7;
    const int cta  = blockIdx.x;
    const int j0   = cta * JPB;

    // ---- this thread's 64 h-part weights in registers (16 x ulonglong2)
    const float* wsrc = (gate == 0) ? wf_w : (gate == 1) ? wi_w : (gate == 2) ? wc_w : wo_w;
    const ulonglong2* wp = (const ulonglong2*)(wsrc + (size_t)(j0 + jj) * ID + CD);
    ulonglong2 wv[KW];
    #pragma unroll
    for (int kk = 0; kk < KW; kk++) wv[kk] = wp[c + 8 * kk];

    // ---- gx (x-part) registers for the JPB owner threads
    const bool owner = (tid < JPB);
    const float* gxp = g_gx + j0 + tid;
    float gxf = 0.f, gxi = 0.f, gxc = 0.f, gxo = 0.f;
    if (owner) {
        gxf = __ldcs(gxp);
        gxi = __ldcs(gxp + CD);
        gxc = __ldcs(gxp + 2 * CD);
        gxo = __ldcs(gxp + 3 * CD);
    }

    float c_state = 0.0f;
    float h_last  = 0.0f;

    unsigned int* myctr = &g_counters[(cta & (NCTR - 1)) * CSTRIDE];

    for (int t = 0; t < T_STEPS; t++) {
        const int b  = t & 1;
        const int b2 = (t + 1) & 1;

        // ---- prefetch next step's x-part (issued before the spin)
        float nf = 0.f, ni = 0.f, nc = 0.f, no = 0.f;
        if (owner && (t + 1) < T_STEPS) {
            const float* p = gxp + (size_t)(t + 1) * NG;
            nf = __ldcs(p);
            ni = __ldcs(p + CD);
            nc = __ldcs(p + 2 * CD);
            no = __ldcs(p + 3 * CD);
        }

        // ---- 8 threads poll 8 split counters in parallel (acquire)
        if (tid < NCTR) {
            const unsigned int* fp = &g_counters[tid * CSTRIDE];
            unsigned int target = (unsigned int)(NB / NCTR) * (unsigned int)t;
            while (ld_acq32(fp) < target) { }
        }
        __syncthreads();                                  // bar1: h(t) published

        // ---- one-shot wide gather of h(t) (.cv, ordered by acquire+bar)
        if (tid < CD / 4) {
            hs4[tid] = __ldcv((const float4*)&g_hbuf[b][4 * tid]);
        }
        __syncthreads();                                  // bar2: h in smem

        // ---- recurrent dot: 64 MACs via 32 packed f32x2 FMAs
        unsigned long long a0 = 0ull, a1 = 0ull, a2 = 0ull, a3 = 0ull;
        #pragma unroll
        for (int kk = 0; kk < KW; kk += 2) {
            ulonglong2 h0 = hs[c + 8 * kk];
            ulonglong2 h1 = hs[c + 8 * (kk + 1)];
            a0 = ffma2(wv[kk].x,     h0.x, a0);
            a1 = ffma2(wv[kk].y,     h0.y, a1);
            a2 = ffma2(wv[kk + 1].x, h1.x, a2);
            a3 = ffma2(wv[kk + 1].y, h1.y, a3);
        }
        float2 u0 = unpack2(a0), u1 = unpack2(a1), u2 = unpack2(a2), u3 = unpack2(a3);
        float acc = ((u0.x + u0.y) + (u1.x + u1.y)) + ((u2.x + u2.y) + (u3.x + u3.y));
        acc += __shfl_down_sync(0xffffffffu, acc, 4);
        acc += __shfl_down_sync(0xffffffffu, acc, 2);
        acc += __shfl_down_sync(0xffffffffu, acc, 1);
        if (c == 0) gsm[r] = acc;
        __syncthreads();                                  // bar3: dots ready

        // ---- gate update (8 owner threads) + data stores
        if (owner) {
            float gf = gsm[tid]      + gxf;
            float gi = gsm[ 8 + tid] + gxi;
            float gc = gsm[16 + tid] + gxc;
            float go = gsm[24 + tid] + gxo;
            float f  = sigmoid_f(gf);
            float ii = sigmoid_f(gi);
            float cc = tanh_f(gc);
            float oo = sigmoid_f(go);
            c_state = f * c_state + ii * cc;
            h_last  = tanh_f(c_state) * oo;
            __stcg(&g_hbuf[b2][j0 + tid], h_last);        // publish h(t+1) data
            gxf = nf; gxi = ni; gxc = nc; gxo = no;
        }
        __syncthreads();                                  // bar4: stores issued
        if (tid == 0)
            red_rel_add(myctr, 1u);                       // release arrival
        // next iteration's acquire-poll completes the barrier
    }

    if (owner) {
        d_out[j0 + tid]      = c_state;   // output = (c, h)
        d_out[CD + j0 + tid] = h_last;
    }
}

// ---------------- launch -----------------------------------------------------
extern "C" void kernel_launch(void* const* d_in, const int* in_sizes, int n_in,
                              void* d_out, int out_size) {
    (void)in_sizes; (void)n_in; (void)out_size;
    const float* x    = (const float*)d_in[0];
    const float* wf_w = (const float*)d_in[1];
    const float* wf_b = (const float*)d_in[2];
    const float* wi_w = (const float*)d_in[3];
    const float* wi_b = (const float*)d_in[4];
    const float* wc_w = (const float*)d_in[5];
    const float* wc_b = (const float*)d_in[6];
    const float* wo_w = (const float*)d_in[7];
    const float* wo_b = (const float*)d_in[8];
    float* out = (float*)d_out;

    dim3 ggrid(NG / GBN, T_STEPS / GBM);
    gemm_gx_kernel<<<ggrid, 256>>>(x, wf_w, wf_b, wi_w, wi_b, wc_w, wc_b, wo_w, wo_b);

    lstm_rec_kernel<<<NB, TPB>>>(wf_w, wi_w, wc_w, wo_w, out);
}

// round 11
// speedup vs baseline: 1.0056x; 1.0056x over previous
#include <cuda_runtime.h>
#include <cstdint>
#include <cstddef>

#define T_STEPS 32768
#define CD 512
#define ID 1024
#define NG 2048
#define NB   64
#define TPB  256
#define JPB  8            // h indices per CTA
#define NROWS 32          // 4 gates * JPB rows per CTA
#define KW   16           // ulonglong2 (4 floats) chunks per lane

// ---------------- device-global scratch ------------------------------------
__device__ float g_gx[(size_t)T_STEPS * NG];   // precomputed Wx@x + b, [T][2048]
__device__ float g_hbuf[2][CD];                // double-buffered h (plain data)
__device__ unsigned int g_counter;             // monotonic arrival counter

// ---------------- morally-strong accessors ----------------------------------
__device__ __forceinline__ unsigned int ld_acq32(const unsigned int* p) {
    unsigned int v;
    asm volatile("ld.acquire.gpu.global.u32 %0, [%1];" : "=r"(v) : "l"(p) : "memory");
    return v;
}
__device__ __forceinline__ void red_rel_add(unsigned int* p, unsigned int v) {
    asm volatile("red.release.gpu.global.add.u32 [%0], %1;" :: "l"(p), "r"(v) : "memory");
}

// ---------------- GEMM (+ inlined state reset in block (0,0)) ---------------
#define GBM 128
#define GBN 128
#define GBK 8

__global__ __launch_bounds__(256) void gemm_gx_kernel(
    const float* __restrict__ x,
    const float* __restrict__ wf_w, const float* __restrict__ wf_b,
    const float* __restrict__ wi_w, const float* __restrict__ wi_b,
    const float* __restrict__ wc_w, const float* __restrict__ wc_b,
    const float* __restrict__ wo_w, const float* __restrict__ wo_b)
{
    // ---- state reset (rec kernel runs only after this grid completes)
    if (blockIdx.x == 0 && blockIdx.y == 0) {
        int i = threadIdx.x;
        if (i < 2 * CD) (&g_hbuf[0][0])[i] = 0.0f;   // h(0) = 0, both buffers
        if (i == 0) g_counter = 0u;
    }

    __shared__ float As[GBK][GBM];
    __shared__ float Bs[GBK][GBN];

    const int tid = threadIdx.x;
    const int tx = tid & 15;
    const int ty = tid >> 4;
    const int r0 = blockIdx.x * GBN;
    const int t0 = blockIdx.y * GBM;
    const int gate = r0 >> 9;
    const int rbase = r0 & 511;

    const float* wsrc = (gate == 0) ? wf_w : (gate == 1) ? wi_w : (gate == 2) ? wc_w : wo_w;
    const float* bsrc = (gate == 0) ? wf_b : (gate == 1) ? wi_b : (gate == 2) ? wc_b : wo_b;

    const int lrow = tid >> 1;
    const int lk4  = (tid & 1) * 4;

    float acc[8][8];
    #pragma unroll
    for (int i = 0; i < 8; i++)
        #pragma unroll
        for (int j = 0; j < 8; j++) acc[i][j] = 0.0f;

    for (int k0 = 0; k0 < CD; k0 += GBK) {
        float4 av = *(const float4*)(x    + (size_t)(t0 + lrow) * CD + k0 + lk4);
        float4 bv = *(const float4*)(wsrc + (size_t)(rbase + lrow) * ID + k0 + lk4);
        __syncthreads();
        As[lk4 + 0][lrow] = av.x; As[lk4 + 1][lrow] = av.y;
        As[lk4 + 2][lrow] = av.z; As[lk4 + 3][lrow] = av.w;
        Bs[lk4 + 0][lrow] = bv.x; Bs[lk4 + 1][lrow] = bv.y;
        Bs[lk4 + 2][lrow] = bv.z; Bs[lk4 + 3][lrow] = bv.w;
        __syncthreads();
        #pragma unroll
        for (int k = 0; k < GBK; k++) {
            const float4* As4 = (const float4*)As[k];
            const float4* Bs4 = (const float4*)Bs[k];
            float4 a0 = As4[ty], a1 = As4[16 + ty];
            float4 b0 = Bs4[tx], b1 = Bs4[16 + tx];
            float ar[8] = {a0.x, a0.y, a0.z, a0.w, a1.x, a1.y, a1.z, a1.w};
            float br[8] = {b0.x, b0.y, b0.z, b0.w, b1.x, b1.y, b1.z, b1.w};
            #pragma unroll
            for (int i = 0; i < 8; i++)
                #pragma unroll
                for (int j = 0; j < 8; j++) acc[i][j] += ar[i] * br[j];
        }
    }

    float4 bias0 = *(const float4*)(bsrc + rbase + tx * 4);
    float4 bias1 = *(const float4*)(bsrc + rbase + 64 + tx * 4);
    float bb[8] = {bias0.x, bias0.y, bias0.z, bias0.w, bias1.x, bias1.y, bias1.z, bias1.w};

    #pragma unroll
    for (int i = 0; i < 8; i++) {
        int trow = t0 + ((i < 4) ? (ty * 4 + i) : (64 + ty * 4 + i - 4));
        float4 o0, o1;
        o0.x = acc[i][0] + bb[0]; o0.y = acc[i][1] + bb[1];
        o0.z = acc[i][2] + bb[2]; o0.w = acc[i][3] + bb[3];
        o1.x = acc[i][4] + bb[4]; o1.y = acc[i][5] + bb[5];
        o1.z = acc[i][6] + bb[6]; o1.w = acc[i][7] + bb[7];
        *(float4*)(g_gx + (size_t)trow * NG + r0 + tx * 4)      = o0;
        *(float4*)(g_gx + (size_t)trow * NG + r0 + 64 + tx * 4) = o1;
    }
}

// ---------------- persistent recurrent kernel --------------------------------
__device__ __forceinline__ unsigned long long ffma2(
    unsigned long long a, unsigned long long b, unsigned long long c) {
    unsigned long long d;
    asm ("fma.rn.f32x2 %0, %1, %2, %3;" : "=l"(d) : "l"(a), "l"(b), "l"(c));
    return d;
}
__device__ __forceinline__ float2 unpack2(unsigned long long a) {
    float2 r;
    asm ("mov.b64 {%0, %1}, %2;" : "=f"(r.x), "=f"(r.y) : "l"(a));
    return r;
}
__device__ __forceinline__ float sigmoid_f(float x) {
    return __fdividef(1.0f, 1.0f + __expf(-x));
}
__device__ __forceinline__ float tanh_f(float x) {
    float ax = fabsf(x);
    float e  = __expf(-2.0f * ax);
    float t  = __fdividef(1.0f - e, 1.0f + e);
    return copysignf(t, x);
}

__global__ __launch_bounds__(TPB, 1) void lstm_rec_kernel(
    const float* __restrict__ wf_w, const float* __restrict__ wi_w,
    const float* __restrict__ wc_w, const float* __restrict__ wo_w,
    float* __restrict__ d_out)
{
    __shared__ __align__(16) float hsf[CD];   // h(t) broadcast
    __shared__ float gsm[NROWS];              // per-row recurrent dots
    __shared__ int go_s;                      // heater wake flag (poller -> heaters)

    const ulonglong2* hs = (const ulonglong2*)hsf;
    float4* hs4 = (float4*)hsf;
    volatile int* gov = &go_s;

    const int tid  = threadIdx.x;
    const int wrp  = tid >> 5;
    const int r    = tid >> 3;          // local row 0..31
    const int c    = tid & 7;           // lane within row
    const int gate = r >> 3;
    const int jj   = r & 7;
    const int cta  = blockIdx.x;
    const int j0   = cta * JPB;

    if (tid == 0) go_s = 0;

    // ---- this thread's 64 h-part weights in registers (16 x ulonglong2)
    const float* wsrc = (gate == 0) ? wf_w : (gate == 1) ? wi_w : (gate == 2) ? wc_w : wo_w;
    const ulonglong2* wp = (const ulonglong2*)(wsrc + (size_t)(j0 + jj) * ID + CD);
    ulonglong2 wv[KW];
    #pragma unroll
    for (int kk = 0; kk < KW; kk++) wv[kk] = wp[c + 8 * kk];

    // ---- gx (x-part) registers for the JPB owner threads (warp 0)
    const bool owner = (tid < JPB);
    const float* gxp = g_gx + j0 + tid;
    float gxf = 0.f, gxi = 0.f, gxc = 0.f, gxo = 0.f;
    if (owner) {
        gxf = __ldcs(gxp);
        gxi = __ldcs(gxp + CD);
        gxc = __ldcs(gxp + 2 * CD);
        gxo = __ldcs(gxp + 3 * CD);
    }

    float c_state = 0.0f;
    float h_last  = 0.0f;

    // heater accumulators (live across the whole kernel)
    float z0 = 1.0f, z1 = 1.1f, z2 = 1.2f, z3 = 1.3f;

    __syncthreads();   // go_s initialized

    for (int t = 0; t < T_STEPS; t++) {
        const int b  = t & 1;
        const int b2 = (t + 1) & 1;

        // ---- prefetch next step's x-part (issued before the spin)
        float nf = 0.f, ni = 0.f, nc = 0.f, no = 0.f;
        if (owner && (t + 1) < T_STEPS) {
            const float* p = gxp + (size_t)(t + 1) * NG;
            nf = __ldcs(p);
            ni = __ldcs(p + CD);
            nc = __ldcs(p + 2 * CD);
            no = __ldcs(p + 3 * CD);
        }

        // ---- spin phase: warp 1 polls the counter; everyone else HEATS
        if (wrp == 1) {
            unsigned int target = (unsigned int)NB * (unsigned int)t;
            while (ld_acq32(&g_counter) < target) { }
            if (tid == 32) go_s = t + 1;      // wake heaters (heuristic only)
        } else {
            while (*gov < t + 1) {            // clock heater: keep fma pipe busy
                #pragma unroll
                for (int q = 0; q < 8; q++) {
                    z0 = __fmaf_rn(z0, 1.0000001f, 1e-9f);
                    z1 = __fmaf_rn(z1, 0.9999999f, 1e-9f);
                    z2 = __fmaf_rn(z2, 1.0000002f, 1e-9f);
                    z3 = __fmaf_rn(z3, 0.9999998f, 1e-9f);
                }
            }
        }
        __syncthreads();                                  // bar1: h(t) published

        // ---- one-shot wide gather of h(t) (.cv, ordered by acquire+bar)
        if (tid < CD / 4) {
            hs4[tid] = __ldcv((const float4*)&g_hbuf[b][4 * tid]);
        }
        __syncthreads();                                  // bar2: h in smem

        // ---- recurrent dot: 64 MACs via 32 packed f32x2 FMAs
        unsigned long long a0 = 0ull, a1 = 0ull, a2 = 0ull, a3 = 0ull;
        #pragma unroll
        for (int kk = 0; kk < KW; kk += 2) {
            ulonglong2 h0 = hs[c + 8 * kk];
            ulonglong2 h1 = hs[c + 8 * (kk + 1)];
            a0 = ffma2(wv[kk].x,     h0.x, a0);
            a1 = ffma2(wv[kk].y,     h0.y, a1);
            a2 = ffma2(wv[kk + 1].x, h1.x, a2);
            a3 = ffma2(wv[kk + 1].y, h1.y, a3);
        }
        float2 u0 = unpack2(a0), u1 = unpack2(a1), u2 = unpack2(a2), u3 = unpack2(a3);
        float acc = ((u0.x + u0.y) + (u1.x + u1.y)) + ((u2.x + u2.y) + (u3.x + u3.y));
        acc += __shfl_down_sync(0xffffffffu, acc, 4);
        acc += __shfl_down_sync(0xffffffffu, acc, 2);
        acc += __shfl_down_sync(0xffffffffu, acc, 1);
        if (c == 0) gsm[r] = acc;
        __syncthreads();                                  // bar3: dots ready

        // ---- gate update (8 owner threads) + data stores
        if (owner) {
            float gf = gsm[tid]      + gxf;
            float gi = gsm[ 8 + tid] + gxi;
            float gc = gsm[16 + tid] + gxc;
            float go = gsm[24 + tid] + gxo;
            float f  = sigmoid_f(gf);
            float ii = sigmoid_f(gi);
            float cc = tanh_f(gc);
            float oo = sigmoid_f(go);
            c_state = f * c_state + ii * cc;
            h_last  = tanh_f(c_state) * oo;
            __stcg(&g_hbuf[b2][j0 + tid], h_last);        // publish h(t+1) data
            gxf = nf; gxi = ni; gxc = nc; gxo = no;
        }
        __syncthreads();                                  // bar4: stores issued
        if (tid == 0)
            red_rel_add(&g_counter, 1u);                  // release arrival
        // next iteration's acquire-poll completes the barrier
    }

    // keep heater registers alive (condition can never be true; opaque via volatile)
    if (*gov == 0x7fffffff && tid == 0)
        g_hbuf[0][0] = z0 + z1 + z2 + z3;

    if (owner) {
        d_out[j0 + tid]      = c_state;   // output = (c, h)
        d_out[CD + j0 + tid] = h_last;
    }
}

// ---------------- launch -----------------------------------------------------
extern "C" void kernel_launch(void* const* d_in, const int* in_sizes, int n_in,
                              void* d_out, int out_size) {
    (void)in_sizes; (void)n_in; (void)out_size;
    const float* x    = (const float*)d_in[0];
    const float* wf_w = (const float*)d_in[1];
    const float* wf_b = (const float*)d_in[2];
    const float* wi_w = (const float*)d_in[3];
    const float* wi_b = (const float*)d_in[4];
    const float* wc_w = (const float*)d_in[5];
    const float* wc_b = (const float*)d_in[6];
    const float* wo_w = (const float*)d_in[7];
    const float* wo_b = (const float*)d_in[8];
    float* out = (float*)d_out;

    dim3 ggrid(NG / GBN, T_STEPS / GBM);
    gemm_gx_kernel<<<ggrid, 256>>>(x, wf_w, wf_b, wi_w, wi_b, wc_w, wc_b, wo_w, wo_b);

    lstm_rec_kernel<<<NB, TPB>>>(wf_w, wi_w, wc_w, wo_w, out);
}

// round 13
// speedup vs baseline: 1.1949x; 1.1883x over previous
#include <cuda_runtime.h>
#include <cstdint>
#include <cstddef>

#define T_STEPS 32768
#define CD 512
#define ID 1024
#define NG 2048
#define NB   64
#define TPB  256
#define JPB  8            // h indices per CTA
#define NROWS 32          // 4 gates * JPB rows per CTA
#define KW   16           // ulonglong2 (4 floats) chunks per lane

// ---------------- device-global scratch ------------------------------------
__device__ float g_gx[(size_t)T_STEPS * NG];   // precomputed Wx@x + b, [T][2048]
// h publication: word j = (h_j bits) | (step tag << 32); owner-written, double buffered
__device__ unsigned long long g_hpub[2][CD];

// ---------------- morally-strong accessors ----------------------------------
__device__ __forceinline__ unsigned long long ld_acq64(const unsigned long long* p) {
    unsigned long long v;
    asm volatile("ld.acquire.gpu.global.b64 %0, [%1];" : "=l"(v) : "l"(p) : "memory");
    return v;
}
__device__ __forceinline__ void st_relax64(unsigned long long* p, unsigned long long v) {
    asm volatile("st.relaxed.gpu.global.b64 [%0], %1;" :: "l"(p), "l"(v) : "memory");
}

// ---------------- GEMM (+ inlined FULL state reset in block (0,0)) ----------
#define GBM 128
#define GBN 128
#define GBK 8

__global__ __launch_bounds__(256) void gemm_gx_kernel(
    const float* __restrict__ x,
    const float* __restrict__ wf_w, const float* __restrict__ wf_b,
    const float* __restrict__ wi_w, const float* __restrict__ wi_b,
    const float* __restrict__ wc_w, const float* __restrict__ wc_b,
    const float* __restrict__ wo_w, const float* __restrict__ wo_b)
{
    // ---- state reset: ALL 1024 tag words, strided over the 256 threads.
    // (Previous round cleared only 256 of 1024 -> stale tags from the prior
    //  replay deadlocked the t=0 poll on every call after the first.)
    if (blockIdx.x == 0 && blockIdx.y == 0) {
        for (int i = threadIdx.x; i < 2 * CD; i += 256)
            (&g_hpub[0][0])[i] = 0ull;   // h(0)=0, tag=0, both buffers
    }

    __shared__ float As[GBK][GBM];
    __shared__ float Bs[GBK][GBN];

    const int tid = threadIdx.x;
    const int tx = tid & 15;
    const int ty = tid >> 4;
    const int r0 = blockIdx.x * GBN;
    const int t0 = blockIdx.y * GBM;
    const int gate = r0 >> 9;
    const int rbase = r0 & 511;

    const float* wsrc = (gate == 0) ? wf_w : (gate == 1) ? wi_w : (gate == 2) ? wc_w : wo_w;
    const float* bsrc = (gate == 0) ? wf_b : (gate == 1) ? wi_b : (gate == 2) ? wc_b : wo_b;

    const int lrow = tid >> 1;
    const int lk4  = (tid & 1) * 4;

    float acc[8][8];
    #pragma unroll
    for (int i = 0; i < 8; i++)
        #pragma unroll
        for (int j = 0; j < 8; j++) acc[i][j] = 0.0f;

    for (int k0 = 0; k0 < CD; k0 += GBK) {
        float4 av = *(const float4*)(x    + (size_t)(t0 + lrow) * CD + k0 + lk4);
        float4 bv = *(const float4*)(wsrc + (size_t)(rbase + lrow) * ID + k0 + lk4);
        __syncthreads();
        As[lk4 + 0][lrow] = av.x; As[lk4 + 1][lrow] = av.y;
        As[lk4 + 2][lrow] = av.z; As[lk4 + 3][lrow] = av.w;
        Bs[lk4 + 0][lrow] = bv.x; Bs[lk4 + 1][lrow] = bv.y;
        Bs[lk4 + 2][lrow] = bv.z; Bs[lk4 + 3][lrow] = bv.w;
        __syncthreads();
        #pragma unroll
        for (int k = 0; k < GBK; k++) {
            const float4* As4 = (const float4*)As[k];
            const float4* Bs4 = (const float4*)Bs[k];
            float4 a0 = As4[ty], a1 = As4[16 + ty];
            float4 b0 = Bs4[tx], b1 = Bs4[16 + tx];
            float ar[8] = {a0.x, a0.y, a0.z, a0.w, a1.x, a1.y, a1.z, a1.w};
            float br[8] = {b0.x, b0.y, b0.z, b0.w, b1.x, b1.y, b1.z, b1.w};
            #pragma unroll
            for (int i = 0; i < 8; i++)
                #pragma unroll
                for (int j = 0; j < 8; j++) acc[i][j] += ar[i] * br[j];
        }
    }

    float4 bias0 = *(const float4*)(bsrc + rbase + tx * 4);
    float4 bias1 = *(const float4*)(bsrc + rbase + 64 + tx * 4);
    float bb[8] = {bias0.x, bias0.y, bias0.z, bias0.w, bias1.x, bias1.y, bias1.z, bias1.w};

    #pragma unroll
    for (int i = 0; i < 8; i++) {
        int trow = t0 + ((i < 4) ? (ty * 4 + i) : (64 + ty * 4 + i - 4));
        float4 o0, o1;
        o0.x = acc[i][0] + bb[0]; o0.y = acc[i][1] + bb[1];
        o0.z = acc[i][2] + bb[2]; o0.w = acc[i][3] + bb[3];
        o1.x = acc[i][4] + bb[4]; o1.y = acc[i][5] + bb[5];
        o1.z = acc[i][6] + bb[6]; o1.w = acc[i][7] + bb[7];
        *(float4*)(g_gx + (size_t)trow * NG + r0 + tx * 4)      = o0;
        *(float4*)(g_gx + (size_t)trow * NG + r0 + 64 + tx * 4) = o1;
    }
}

// ---------------- persistent recurrent kernel --------------------------------
__device__ __forceinline__ unsigned long long ffma2(
    unsigned long long a, unsigned long long b, unsigned long long c) {
    unsigned long long d;
    asm ("fma.rn.f32x2 %0, %1, %2, %3;" : "=l"(d) : "l"(a), "l"(b), "l"(c));
    return d;
}
__device__ __forceinline__ float2 unpack2(unsigned long long a) {
    float2 r;
    asm ("mov.b64 {%0, %1}, %2;" : "=f"(r.x), "=f"(r.y) : "l"(a));
    return r;
}
__device__ __forceinline__ float sigmoid_f(float x) {
    return __fdividef(1.0f, 1.0f + __expf(-x));
}
__device__ __forceinline__ float tanh_f(float x) {
    float ax = fabsf(x);
    float e  = __expf(-2.0f * ax);
    float t  = __fdividef(1.0f - e, 1.0f + e);
    return copysignf(t, x);
}

__global__ __launch_bounds__(TPB, 1) void lstm_rec_kernel(
    const float* __restrict__ wf_w, const float* __restrict__ wi_w,
    const float* __restrict__ wc_w, const float* __restrict__ wo_w,
    float* __restrict__ d_out)
{
    __shared__ __align__(16) float hsf[CD];   // h(t) broadcast
    __shared__ float gsm[NROWS];              // ACTIVATED per-row gate values

    const ulonglong2* hs = (const ulonglong2*)hsf;
    unsigned long long* hsll = (unsigned long long*)hsf;

    const int tid  = threadIdx.x;
    const int r    = tid >> 3;          // local row 0..31
    const int c    = tid & 7;           // lane within row
    const int gate = r >> 3;
    const int jj   = r & 7;
    const int cta  = blockIdx.x;
    const int j0   = cta * JPB;
    const bool rowner = (c == 0);       // 32 row-owner threads (activations)
    const bool owner  = (tid < JPB);    // 8 h-owner threads (state + publish)

    // ---- this thread's 64 h-part weights in registers (16 x ulonglong2)
    const float* wsrc = (gate == 0) ? wf_w : (gate == 1) ? wi_w : (gate == 2) ? wc_w : wo_w;
    const ulonglong2* wp = (const ulonglong2*)(wsrc + (size_t)(j0 + jj) * ID + CD);
    ulonglong2 wv[KW];
    #pragma unroll
    for (int kk = 0; kk < KW; kk++) wv[kk] = wp[c + 8 * kk];

    // ---- per-ROW gx pointer (32 row-owners each prefetch their own gate value)
    const float* gxrow = g_gx + (size_t)gate * CD + j0 + jj;
    float gx_cur = rowner ? __ldcs(gxrow) : 0.0f;

    float c_state = 0.0f;
    float h_last  = 0.0f;

    for (int t = 0; t < T_STEPS; t++) {
        const int b  = t & 1;
        const int b2 = (t + 1) & 1;
        const unsigned int ut = (unsigned int)t;

        // ---- prefetch next step's gx (flies during the poll)
        float gx_next = 0.0f;
        if (rowner && (t + 1) < T_STEPS)
            gx_next = __ldcs(gxrow + (size_t)(t + 1) * NG);

        // ---- single-RTT detect+gather: poll BOTH words each iteration (MLP=2)
        const unsigned long long* w0 = &g_hpub[b][2 * tid];
        unsigned long long v0 = ld_acq64(w0);
        unsigned long long v1 = ld_acq64(w0 + 1);
        while (((unsigned)(v0 >> 32) != ut) | ((unsigned)(v1 >> 32) != ut)) {
            v0 = ld_acq64(w0);
            v1 = ld_acq64(w0 + 1);
        }
        hsll[tid] = (v0 & 0xffffffffull) | (v1 << 32);   // STS.64: two h floats
        __syncthreads();                                  // bar1: h(t) in smem

        // ---- recurrent dot: 64 MACs via 32 packed f32x2 FMAs
        unsigned long long a0 = 0ull, a1 = 0ull, a2 = 0ull, a3 = 0ull;
        #pragma unroll
        for (int kk = 0; kk < KW; kk += 2) {
            ulonglong2 h0 = hs[c + 8 * kk];
            ulonglong2 h1 = hs[c + 8 * (kk + 1)];
            a0 = ffma2(wv[kk].x,     h0.x, a0);
            a1 = ffma2(wv[kk].y,     h0.y, a1);
            a2 = ffma2(wv[kk + 1].x, h1.x, a2);
            a3 = ffma2(wv[kk + 1].y, h1.y, a3);
        }
        float2 u0 = unpack2(a0), u1 = unpack2(a1), u2 = unpack2(a2), u3 = unpack2(a3);
        float acc = ((u0.x + u0.y) + (u1.x + u1.y)) + ((u2.x + u2.y) + (u3.x + u3.y));
        acc += __shfl_down_sync(0xffffffffu, acc, 4);
        acc += __shfl_down_sync(0xffffffffu, acc, 2);
        acc += __shfl_down_sync(0xffffffffu, acc, 1);

        // ---- parallel activations: 32 row-owners activate their gate value
        if (rowner) {
            float g = acc + gx_cur;
            gsm[r] = (gate == 2) ? tanh_f(g) : sigmoid_f(g);
            gx_cur = gx_next;
        }
        __syncthreads();                                  // bar2: activated gates ready

        // ---- state update + one-store publish (8 owner threads)
        if (owner) {
            float f  = gsm[tid];
            float ii = gsm[ 8 + tid];
            float cc = gsm[16 + tid];
            float oo = gsm[24 + tid];
            c_state = f * c_state + ii * cc;
            h_last  = tanh_f(c_state) * oo;
            unsigned long long pv = (unsigned long long)__float_as_uint(h_last)
                                  | ((unsigned long long)(ut + 1u) << 32);
            st_relax64(&g_hpub[b2][j0 + tid], pv);        // data + tag, one store
        }
        // no trailing barrier: next poll is the global step barrier
    }

    if (owner) {
        d_out[j0 + tid]      = c_state;   // output = (c, h)
        d_out[CD + j0 + tid] = h_last;
    }
}

// ---------------- launch -----------------------------------------------------
extern "C" void kernel_launch(void* const* d_in, const int* in_sizes, int n_in,
                              void* d_out, int out_size) {
    (void)in_sizes; (void)n_in; (void)out_size;
    const float* x    = (const float*)d_in[0];
    const float* wf_w = (const float*)d_in[1];
    const float* wf_b = (const float*)d_in[2];
    const float* wi_w = (const float*)d_in[3];
    const float* wi_b = (const float*)d_in[4];
    const float* wc_w = (const float*)d_in[5];
    const float* wc_b = (const float*)d_in[6];
    const float* wo_w = (const float*)d_in[7];
    const float* wo_b = (const float*)d_in[8];
    float* out = (float*)d_out;

    dim3 ggrid(NG / GBN, T_STEPS / GBM);
    gemm_gx_kernel<<<ggrid, 256>>>(x, wf_w, wf_b, wi_w, wi_b, wc_w, wc_b, wo_w, wo_b);

    lstm_rec_kernel<<<NB, TPB>>>(wf_w, wi_w, wc_w, wo_w, out);
}